// round 13
// baseline (speedup 1.0000x reference)
#include <cuda_runtime.h>
#include <cuda_bf16.h>
#include <cuda_fp16.h>
#include <cstdint>

#define Nn 50000
#define IN_D 32
#define HID 128
#define OUT_D 10
#define NUM_K 5
#define EK 400000
#define NG 500
#define NC 15
#define RH 192
#define R1IN 384

// ---------------- scratch (device globals) ----------------
__device__ __align__(256) __half g_hist[6 * Nn * HID];      // h0..h5 (fp16 storage, f32 math)
__device__ __align__(256) __half g_z[NUM_K * Nn * HID];     // aggregated inputs (fp16)
__device__ __align__(256) __half g_Wfhi[NC * HID * HID];    // W/k fp16 hi, row-major [ci][n][k]
__device__ __align__(256) __half g_Wflo[NC * HID * HID];    // fp16 lo residual
__device__ __align__(256) float g_blayer[5 * HID];
__device__ __align__(256) float g_r1Wt[R1IN * RH];
__device__ __align__(256) float g_r2Wt[RH * OUT_D];
__device__ __align__(256) float g_dinv[NUM_K * Nn];
__device__ __align__(256) unsigned g_degcnt[NUM_K * Nn];
__device__ __align__(256) int g_rowstart[NUM_K * Nn];
__device__ __align__(256) int g_cursor[NUM_K * Nn];
__device__ __align__(256) int g_ctr[NUM_K];
__device__ __align__(256) int g_csr_src[NUM_K * EK];
__device__ __align__(256) float g_ssum[NG * HID];
__device__ __align__(256) float g_smax[NG * HID];
__device__ __align__(256) float g_cnt[NG];
__device__ __align__(256) float g_hid[NG * RH];

__constant__ int c_kval[NC] = {1, 1,2, 1,2,3, 1,2,3,4, 1,2,3,4,5};
__constant__ int c_ci0[5]   = {0, 1, 3, 6, 10};

// ---------------- helpers ----------------
__device__ __forceinline__ void mma_f16(float* c, const uint32_t* a, uint32_t b0, uint32_t b1) {
    asm volatile(
        "mma.sync.aligned.m16n8k16.row.col.f32.f16.f16.f32 "
        "{%0,%1,%2,%3}, {%4,%5,%6,%7}, {%8,%9}, {%0,%1,%2,%3};"
        : "+f"(c[0]), "+f"(c[1]), "+f"(c[2]), "+f"(c[3])
        : "r"(a[0]), "r"(a[1]), "r"(a[2]), "r"(a[3]), "r"(b0), "r"(b1));
}
// accumulate 8 halves (16B, uint4) scaled by c into 8 float sums
__device__ __forceinline__ void acc8(float* s, uint4 v, float c) {
    __half2 h0 = *(__half2*)&v.x, h1 = *(__half2*)&v.y;
    __half2 h2 = *(__half2*)&v.z, h3 = *(__half2*)&v.w;
    float2 f0 = __half22float2(h0), f1 = __half22float2(h1);
    float2 f2 = __half22float2(h2), f3 = __half22float2(h3);
    s[0] += c * f0.x; s[1] += c * f0.y;
    s[2] += c * f1.x; s[3] += c * f1.y;
    s[4] += c * f2.x; s[5] += c * f2.y;
    s[6] += c * f3.x; s[7] += c * f3.y;
}

// ---------------- setup kernels ----------------
__global__ void prep_weights(const float* __restrict__ r1W, const float* __restrict__ r2W) {
    int idx = blockIdx.x * blockDim.x + threadIdx.x;
    if (idx < RH * R1IN) {
        int j = idx / R1IN, c = idx - j * R1IN;
        g_r1Wt[c * RH + j] = r1W[idx];
    }
    if (idx < OUT_D * RH) {
        int o = idx / RH, c = idx - o * RH;
        g_r2Wt[c * OUT_D + o] = r2W[idx];
    }
}
__global__ void prep_wbf(const float* __restrict__ convW) {
    int idx = blockIdx.x * blockDim.x + threadIdx.x;
    if (idx >= NC * HID * HID) return;
    int ci = idx / (HID * HID);
    float w = convW[idx] / (float)c_kval[ci];
    __half hi = __float2half_rn(w);
    __half lo = __float2half_rn(w - __half2float(hi));
    g_Wfhi[idx] = hi;
    g_Wflo[idx] = lo;
}
__global__ void prep_bias(const float* __restrict__ convb) {
    int j = threadIdx.x;  // 128
    for (int l = 0; l < 5; l++) {
        float s = 0.f;
        for (int kk = 0; kk <= l; kk++)
            s += convb[(c_ci0[l] + kk) * HID + j] / (float)(kk + 1);
        g_blayer[l * HID + j] = s;
    }
}

// ---------------- CSR build (+ pooling buffer zero, fused) ----------------
__global__ void csr_zero() {
    int idx = blockIdx.x * blockDim.x + threadIdx.x;
    if (idx < NUM_K * Nn) g_degcnt[idx] = 0u;
    if (idx < NUM_K) g_ctr[idx] = 0;
    if (idx < NG * HID) { g_ssum[idx] = 0.0f; g_smax[idx] = 0.0f; }
    if (idx < NG) g_cnt[idx] = 0.0f;
}
__global__ void csr_count(const int* __restrict__ dst_all) {
    int e = blockIdx.x * blockDim.x + threadIdx.x;
    if (e < NUM_K * EK) {
        int k = e / EK;
        atomicAdd(&g_degcnt[k * Nn + dst_all[e]], 1u);
    }
}
#define WPK ((Nn + 31) / 32)
__global__ void csr_alloc() {
    int gw = (blockIdx.x * blockDim.x + threadIdx.x) >> 5;
    int lane = threadIdx.x & 31;
    int k = gw / WPK;
    if (k >= NUM_K) return;
    int d = (gw - k * WPK) * 32 + lane;
    int c = (d < Nn) ? (int)g_degcnt[k * Nn + d] : 0;
    int incl = c;
#pragma unroll
    for (int off = 1; off < 32; off <<= 1) {
        int t = __shfl_up_sync(0xffffffff, incl, off);
        if (lane >= off) incl += t;
    }
    int total = __shfl_sync(0xffffffff, incl, 31);
    int base = 0;
    if (lane == 0) base = atomicAdd(&g_ctr[k], total);
    base = __shfl_sync(0xffffffff, base, 0);
    if (d < Nn) {
        int rs = base + incl - c;
        g_rowstart[k * Nn + d] = rs;
        g_cursor[k * Nn + d] = rs;
        g_dinv[k * Nn + d] = rsqrtf((float)c + 1.0f);
    }
}
__global__ void csr_fill(const int* __restrict__ ke) {
    int e = blockIdx.x * blockDim.x + threadIdx.x;
    if (e >= NUM_K * EK) return;
    int k = e / EK;
    int s = ke[e];
    int d = ke[NUM_K * EK + e];
    int pos = atomicAdd(&g_cursor[k * Nn + d], 1);
    g_csr_src[k * EK + pos] = s;
}

// ---------------- embedding ----------------
__global__ void embed_kernel(const float* __restrict__ x,
                             const float* __restrict__ W,
                             const float* __restrict__ b) {
    __shared__ float ws[HID * 33];
    __shared__ float xs[16 * IN_D];
    int tid = threadIdx.x;              // 128
    int row0 = blockIdx.x * 16;
    for (int i = tid; i < HID * IN_D; i += 128) {
        int j = i / IN_D, kk = i - j * IN_D;
        ws[j * 33 + kk] = W[i];
    }
    for (int i = tid; i < 16 * IN_D; i += 128) xs[i] = x[row0 * IN_D + i];
    __syncthreads();
    float acc[16];
    float bb = b[tid];
#pragma unroll
    for (int r = 0; r < 16; r++) acc[r] = bb;
    for (int kk = 0; kk < IN_D; kk++) {
        float w = ws[tid * 33 + kk];
#pragma unroll
        for (int r = 0; r < 16; r++) acc[r] += xs[r * IN_D + kk] * w;
    }
#pragma unroll
    for (int r = 0; r < 16; r++)
        g_hist[(row0 + r) * HID + tid] = __float2half(acc[r]);
}

// ---------------- gather: 2 rows/warp, unroll-8 batched pipeline ----------------
// z_k[d] = dinv_d*(sum_e dinv_s*h[s] + dinv_d*h[d]); fp16 output
// For layer l: blockIdx.y = km1 in [0, l]; input layer = l - km1.
__global__ __launch_bounds__(256) void gather_kernel(int l) {
    int warp = (blockIdx.x * 256 + threadIdx.x) >> 5;
    int lane = threadIdx.x & 31;
    int half = lane >> 4;                // 0 or 1
    int lx = lane & 15;                  // lane within half-warp
    int row = warp * 2 + half;
    if (row >= Nn) return;
    int km1 = blockIdx.y;
    int inlayer = l - km1;
    int e0 = g_rowstart[km1 * Nn + row];
    int e1 = e0 + (int)g_degcnt[km1 * Nn + row];
    const int* srcs = g_csr_src + km1 * EK;
    const float* dv = g_dinv + km1 * Nn;
    const __half* hin = g_hist + (size_t)inlayer * Nn * HID;
    float sum[8];
#pragma unroll
    for (int i = 0; i < 8; i++) sum[i] = 0.f;
    int e = e0;
    // batched pipeline: 8 idx loads -> 8 coef loads -> 8 row loads -> FMAs
    for (; e + 7 < e1; e += 8) {
        int s[8];
#pragma unroll
        for (int j = 0; j < 8; j++) s[j] = srcs[e + j];
        float c[8];
#pragma unroll
        for (int j = 0; j < 8; j++) c[j] = dv[s[j]];
        uint4 v[8];
#pragma unroll
        for (int j = 0; j < 8; j++)
            v[j] = *(const uint4*)&hin[(size_t)s[j] * HID + lx * 8];
#pragma unroll
        for (int j = 0; j < 8; j++) acc8(sum, v[j], c[j]);
    }
    if (e + 3 < e1) {
        int s[4];
#pragma unroll
        for (int j = 0; j < 4; j++) s[j] = srcs[e + j];
        float c[4];
#pragma unroll
        for (int j = 0; j < 4; j++) c[j] = dv[s[j]];
        uint4 v[4];
#pragma unroll
        for (int j = 0; j < 4; j++)
            v[j] = *(const uint4*)&hin[(size_t)s[j] * HID + lx * 8];
#pragma unroll
        for (int j = 0; j < 4; j++) acc8(sum, v[j], c[j]);
        e += 4;
    }
    for (; e < e1; e++) {
        int s0 = srcs[e];
        float c0 = dv[s0];
        uint4 v0 = *(const uint4*)&hin[(size_t)s0 * HID + lx * 8];
        acc8(sum, v0, c0);
    }
    float dd = dv[row];
    uint4 sfv = *(const uint4*)&hin[(size_t)row * HID + lx * 8];
    float self[8];
    {
        __half2 h0 = *(__half2*)&sfv.x, h1 = *(__half2*)&sfv.y;
        __half2 h2 = *(__half2*)&sfv.z, h3 = *(__half2*)&sfv.w;
        float2 f0 = __half22float2(h0), f1 = __half22float2(h1);
        float2 f2 = __half22float2(h2), f3 = __half22float2(h3);
        self[0] = f0.x; self[1] = f0.y; self[2] = f1.x; self[3] = f1.y;
        self[4] = f2.x; self[5] = f2.y; self[6] = f3.x; self[7] = f3.y;
    }
    __half2 r0 = __floats2half2_rn(dd * (sum[0] + dd * self[0]), dd * (sum[1] + dd * self[1]));
    __half2 r1 = __floats2half2_rn(dd * (sum[2] + dd * self[2]), dd * (sum[3] + dd * self[3]));
    __half2 r2 = __floats2half2_rn(dd * (sum[4] + dd * self[4]), dd * (sum[5] + dd * self[5]));
    __half2 r3 = __floats2half2_rn(dd * (sum[6] + dd * self[6]), dd * (sum[7] + dd * self[7]));
    uint4 st;
    st.x = *(uint32_t*)&r0; st.y = *(uint32_t*)&r1;
    st.z = *(uint32_t*)&r2; st.w = *(uint32_t*)&r3;
    size_t ofs = (size_t)km1 * Nn * HID + (size_t)row * HID + lx * 8;
    *(uint4*)&g_z[ofs] = st;
}

// ---------------- layer GEMM via mma.sync f16 (A single, W hi/lo) ----------------
#define ASTR 136                        // fp16 elements per smem row (conflict-free)
#define TILE_B (128 * ASTR * 2)         // 34816 bytes per tile
#define OFF_A 0
#define OFF_WHI TILE_B
#define OFF_WLO (2 * TILE_B)
#define DYN_SMEM (3 * TILE_B)

__global__ __launch_bounds__(256, 1) void layer_gemm(int l, int nk) {
    extern __shared__ char smem[];
    int tid = threadIdx.x;
    int wid = tid >> 5, lane = tid & 31;
    int row0 = blockIdx.x * 128;
    int qr = lane >> 2;          // 0..7
    int qc = (lane & 3) * 2;     // 0,2,4,6
    int wm = (wid & 3) * 32;     // warp row offset
    int wn = (wid >> 2) * 64;    // warp col offset

    float acc[2][8][4];
#pragma unroll
    for (int mt = 0; mt < 2; mt++)
#pragma unroll
        for (int nt = 0; nt < 8; nt++)
#pragma unroll
            for (int c = 0; c < 4; c++) acc[mt][nt][c] = 0.f;

    int ci0 = c_ci0[l];
    for (int kk = 0; kk < nk; kk++) {
        // stage tiles: z (this block's rows) and W hi/lo, re-strided to ASTR
        const float4* za = (const float4*)(g_z + (size_t)kk * Nn * HID);
        const float4* wh = (const float4*)(g_Wfhi + (size_t)(ci0 + kk) * HID * HID);
        const float4* wl = (const float4*)(g_Wflo + (size_t)(ci0 + kk) * HID * HID);
        for (int i = tid; i < 128 * 16; i += 256) {
            int r = i >> 4, c = i & 15;          // c in float4 (8 fp16) units
            int gr = row0 + r;
            float4 va = make_float4(0.f, 0.f, 0.f, 0.f);
            if (gr < Nn) va = za[(size_t)gr * 16 + c];
            size_t dofs = (size_t)r * (ASTR * 2) + c * 16;
            *(float4*)(smem + OFF_A + dofs) = va;
            *(float4*)(smem + OFF_WHI + dofs) = wh[i];
            *(float4*)(smem + OFF_WLO + dofs) = wl[i];
        }
        __syncthreads();

#pragma unroll
        for (int ks = 0; ks < 8; ks++) {
            int k0 = ks * 16;
            uint32_t ah[2][4];
#pragma unroll
            for (int mt = 0; mt < 2; mt++) {
                int r = wm + mt * 16 + qr;
                size_t b0 = (size_t)r * (ASTR * 2) + (k0 + qc) * 2;
                size_t b8 = b0 + 8 * (ASTR * 2);
                ah[mt][0] = *(const uint32_t*)(smem + OFF_A + b0);
                ah[mt][1] = *(const uint32_t*)(smem + OFF_A + b8);
                ah[mt][2] = *(const uint32_t*)(smem + OFF_A + b0 + 16);
                ah[mt][3] = *(const uint32_t*)(smem + OFF_A + b8 + 16);
            }
#pragma unroll
            for (int nt = 0; nt < 8; nt++) {
                int n = wn + nt * 8 + qr;
                size_t b0 = (size_t)n * (ASTR * 2) + (k0 + qc) * 2;
                uint32_t bh0 = *(const uint32_t*)(smem + OFF_WHI + b0);
                uint32_t bh1 = *(const uint32_t*)(smem + OFF_WHI + b0 + 16);
                uint32_t bl0 = *(const uint32_t*)(smem + OFF_WLO + b0);
                uint32_t bl1 = *(const uint32_t*)(smem + OFF_WLO + b0 + 16);
#pragma unroll
                for (int mt = 0; mt < 2; mt++) {
                    mma_f16(acc[mt][nt], ah[mt], bh0, bh1);
                    mma_f16(acc[mt][nt], ah[mt], bl0, bl1);
                }
            }
        }
        __syncthreads();
    }

    // epilogue: bias + relu, fp16 stores
    const float* bl_ = g_blayer + l * HID;
    __half* hout = g_hist + (size_t)(l + 1) * Nn * HID;
#pragma unroll
    for (int mt = 0; mt < 2; mt++) {
        int r = row0 + wm + mt * 16 + qr;
#pragma unroll
        for (int nt = 0; nt < 8; nt++) {
            int col = wn + nt * 8 + qc;
            float b0v = __ldg(&bl_[col]), b1v = __ldg(&bl_[col + 1]);
            if (r < Nn) {
                __half2 v = __floats2half2_rn(fmaxf(acc[mt][nt][0] + b0v, 0.f),
                                              fmaxf(acc[mt][nt][1] + b1v, 0.f));
                *(__half2*)&hout[(size_t)r * HID + col] = v;
            }
            if (r + 8 < Nn) {
                __half2 v = __floats2half2_rn(fmaxf(acc[mt][nt][2] + b0v, 0.f),
                                              fmaxf(acc[mt][nt][3] + b1v, 0.f));
                *(__half2*)&hout[(size_t)(r + 8) * HID + col] = v;
            }
        }
    }
}

// ---------------- pooling + readout ----------------
__global__ void pool_seg(const int* __restrict__ batch) {
    int n0 = blockIdx.x * 128;
    int tid = threadIdx.x;
    const __half* h = g_hist + (size_t)5 * Nn * HID;
    int nend = min(n0 + 128, Nn);
    int cur = batch[n0];
    float sum = 0.f, mx = 0.f;
    int cnt = 0;
    for (int n = n0; n < nend; n++) {
        int b = __ldg(&batch[n]);
        if (b != cur) {
            atomicAdd(&g_ssum[cur * HID + tid], sum);
            atomicMax((int*)&g_smax[cur * HID + tid], __float_as_int(mx));
            if (tid == 0) atomicAdd(&g_cnt[cur], (float)cnt);
            sum = 0.f; mx = 0.f; cnt = 0; cur = b;
        }
        float v = __half2float(h[(size_t)n * HID + tid]);
        sum += v; mx = fmaxf(mx, v); cnt++;
    }
    atomicAdd(&g_ssum[cur * HID + tid], sum);
    atomicMax((int*)&g_smax[cur * HID + tid], __float_as_int(mx));
    if (tid == 0) atomicAdd(&g_cnt[cur], (float)cnt);
}
__global__ void r1_kernel(const float* __restrict__ r1b) {
    __shared__ float ps[R1IN];
    int g = blockIdx.x, tid = threadIdx.x; // 192
    if (tid < HID) {
        float s = g_ssum[g * HID + tid];
        float m = g_smax[g * HID + tid];
        float c = g_cnt[g];
        ps[tid] = s;
        ps[HID + tid] = m;
        ps[2 * HID + tid] = s / fmaxf(c, 1.0f);
    }
    __syncthreads();
    float acc = r1b[tid];
    for (int c = 0; c < R1IN; c++) acc += ps[c] * g_r1Wt[c * RH + tid];
    g_hid[g * RH + tid] = acc > 0.0f ? acc : 0.01f * acc;
}
__global__ void r2_kernel(const float* __restrict__ r2b, float* __restrict__ out) {
    int idx = blockIdx.x * blockDim.x + threadIdx.x;
    if (idx >= NG * OUT_D) return;
    int g = idx / OUT_D, o = idx - g * OUT_D;
    float acc = r2b[o];
    for (int c = 0; c < RH; c++) acc += g_hid[g * RH + c] * g_r2Wt[c * OUT_D + o];
    out[idx] = acc;
}

extern "C" void kernel_launch(void* const* d_in, const int* in_sizes, int n_in,
                              void* d_out, int out_size) {
    const float* x     = (const float*)d_in[0];
    const int*   ke    = (const int*)d_in[1];
    // d_in[2] = k_idx (unused)
    const int*   batch = (const int*)d_in[3];
    const float* embW  = (const float*)d_in[4];
    const float* embb  = (const float*)d_in[5];
    const float* convW = (const float*)d_in[6];
    const float* convb = (const float*)d_in[7];
    const float* r1W   = (const float*)d_in[8];
    const float* r1b   = (const float*)d_in[9];
    const float* r2W   = (const float*)d_in[10];
    const float* r2b   = (const float*)d_in[11];
    float* out = (float*)d_out;

    cudaFuncSetAttribute(layer_gemm, cudaFuncAttributeMaxDynamicSharedMemorySize, DYN_SMEM);

    prep_weights<<<(RH * R1IN + 255) / 256, 256>>>(r1W, r2W);
    prep_wbf<<<(NC * HID * HID + 255) / 256, 256>>>(convW);
    prep_bias<<<1, 128>>>(convb);
    csr_zero<<<(NUM_K * Nn + 255) / 256, 256>>>();
    csr_count<<<(NUM_K * EK + 255) / 256, 256>>>(ke + NUM_K * EK);
    csr_alloc<<<(NUM_K * WPK * 32 + 255) / 256, 256>>>();
    csr_fill<<<(NUM_K * EK + 255) / 256, 256>>>(ke);
    embed_kernel<<<Nn / 16, 128>>>(x, embW, embb);

    for (int l = 0; l <= 4; l++) {
        // 16 rows per block (8 warps x 2 rows)
        dim3 ggrid((Nn + 15) / 16, l + 1);
        gather_kernel<<<ggrid, 256>>>(l);
        layer_gemm<<<(Nn + 127) / 128, 256, DYN_SMEM>>>(l, l + 1);
    }

    pool_seg<<<(Nn + 127) / 128, 128>>>(batch);
    r1_kernel<<<NG, RH>>>(r1b);
    r2_kernel<<<(NG * OUT_D + 255) / 256, 256>>>(r2b, out);
}

// round 14
// speedup vs baseline: 1.1093x; 1.1093x over previous
#include <cuda_runtime.h>
#include <cuda_bf16.h>
#include <cuda_fp16.h>
#include <cstdint>

#define Nn 50000
#define IN_D 32
#define HID 128
#define OUT_D 10
#define NUM_K 5
#define EK 400000
#define NG 500
#define NC 15
#define RH 192
#define R1IN 384

// ---------------- scratch (device globals) ----------------
__device__ __align__(256) __half g_hist[6 * Nn * HID];      // h0..h5 (fp16 storage, f32 math)
__device__ __align__(256) __half g_z[NC * Nn * HID];        // triangular z store: slot = c_ci0[l]+km1
__device__ __align__(256) __half g_Wfhi[NC * HID * HID];    // W/k fp16 hi, row-major [ci][n][k]
__device__ __align__(256) __half g_Wflo[NC * HID * HID];    // fp16 lo residual
__device__ __align__(256) float g_blayer[5 * HID];
__device__ __align__(256) float g_r1Wt[R1IN * RH];
__device__ __align__(256) float g_r2Wt[RH * OUT_D];
__device__ __align__(256) float g_dinv[NUM_K * Nn];
__device__ __align__(256) unsigned g_degcnt[NUM_K * Nn];
__device__ __align__(256) int g_rowstart[NUM_K * Nn];
__device__ __align__(256) int g_cursor[NUM_K * Nn];
__device__ __align__(256) int g_ctr[NUM_K];
__device__ __align__(256) int g_csr_src[NUM_K * EK];
__device__ __align__(256) float g_ssum[NG * HID];
__device__ __align__(256) float g_smax[NG * HID];
__device__ __align__(256) float g_cnt[NG];
__device__ __align__(256) float g_hid[NG * RH];

__constant__ int c_kval[NC] = {1, 1,2, 1,2,3, 1,2,3,4, 1,2,3,4,5};
__constant__ int c_ci0[5]   = {0, 1, 3, 6, 10};

// ---------------- helpers ----------------
__device__ __forceinline__ void mma_f16(float* c, const uint32_t* a, uint32_t b0, uint32_t b1) {
    asm volatile(
        "mma.sync.aligned.m16n8k16.row.col.f32.f16.f16.f32 "
        "{%0,%1,%2,%3}, {%4,%5,%6,%7}, {%8,%9}, {%0,%1,%2,%3};"
        : "+f"(c[0]), "+f"(c[1]), "+f"(c[2]), "+f"(c[3])
        : "r"(a[0]), "r"(a[1]), "r"(a[2]), "r"(a[3]), "r"(b0), "r"(b1));
}
// accumulate 8 halves (16B, uint4) scaled by c into 8 float sums
__device__ __forceinline__ void acc8(float* s, uint4 v, float c) {
    __half2 h0 = *(__half2*)&v.x, h1 = *(__half2*)&v.y;
    __half2 h2 = *(__half2*)&v.z, h3 = *(__half2*)&v.w;
    float2 f0 = __half22float2(h0), f1 = __half22float2(h1);
    float2 f2 = __half22float2(h2), f3 = __half22float2(h3);
    s[0] += c * f0.x; s[1] += c * f0.y;
    s[2] += c * f1.x; s[3] += c * f1.y;
    s[4] += c * f2.x; s[5] += c * f2.y;
    s[6] += c * f3.x; s[7] += c * f3.y;
}

// ---------------- setup kernels ----------------
__global__ void prep_weights(const float* __restrict__ r1W, const float* __restrict__ r2W) {
    int idx = blockIdx.x * blockDim.x + threadIdx.x;
    if (idx < RH * R1IN) {
        int j = idx / R1IN, c = idx - j * R1IN;
        g_r1Wt[c * RH + j] = r1W[idx];
    }
    if (idx < OUT_D * RH) {
        int o = idx / RH, c = idx - o * RH;
        g_r2Wt[c * OUT_D + o] = r2W[idx];
    }
}
__global__ void prep_wbf(const float* __restrict__ convW) {
    int idx = blockIdx.x * blockDim.x + threadIdx.x;
    if (idx >= NC * HID * HID) return;
    int ci = idx / (HID * HID);
    float w = convW[idx] / (float)c_kval[ci];
    __half hi = __float2half_rn(w);
    __half lo = __float2half_rn(w - __half2float(hi));
    g_Wfhi[idx] = hi;
    g_Wflo[idx] = lo;
}
__global__ void prep_bias(const float* __restrict__ convb) {
    int j = threadIdx.x;  // 128
    for (int l = 0; l < 5; l++) {
        float s = 0.f;
        for (int kk = 0; kk <= l; kk++)
            s += convb[(c_ci0[l] + kk) * HID + j] / (float)(kk + 1);
        g_blayer[l * HID + j] = s;
    }
}

// ---------------- CSR build (+ pooling buffer zero, fused) ----------------
__global__ void csr_zero() {
    int idx = blockIdx.x * blockDim.x + threadIdx.x;
    if (idx < NUM_K * Nn) g_degcnt[idx] = 0u;
    if (idx < NUM_K) g_ctr[idx] = 0;
    if (idx < NG * HID) { g_ssum[idx] = 0.0f; g_smax[idx] = 0.0f; }
    if (idx < NG) g_cnt[idx] = 0.0f;
}
__global__ void csr_count(const int* __restrict__ dst_all) {
    int e = blockIdx.x * blockDim.x + threadIdx.x;
    if (e < NUM_K * EK) {
        int k = e / EK;
        atomicAdd(&g_degcnt[k * Nn + dst_all[e]], 1u);
    }
}
#define WPK ((Nn + 31) / 32)
__global__ void csr_alloc() {
    int gw = (blockIdx.x * blockDim.x + threadIdx.x) >> 5;
    int lane = threadIdx.x & 31;
    int k = gw / WPK;
    if (k >= NUM_K) return;
    int d = (gw - k * WPK) * 32 + lane;
    int c = (d < Nn) ? (int)g_degcnt[k * Nn + d] : 0;
    int incl = c;
#pragma unroll
    for (int off = 1; off < 32; off <<= 1) {
        int t = __shfl_up_sync(0xffffffff, incl, off);
        if (lane >= off) incl += t;
    }
    int total = __shfl_sync(0xffffffff, incl, 31);
    int base = 0;
    if (lane == 0) base = atomicAdd(&g_ctr[k], total);
    base = __shfl_sync(0xffffffff, base, 0);
    if (d < Nn) {
        int rs = base + incl - c;
        g_rowstart[k * Nn + d] = rs;
        g_cursor[k * Nn + d] = rs;
        g_dinv[k * Nn + d] = rsqrtf((float)c + 1.0f);
    }
}
__global__ void csr_fill(const int* __restrict__ ke) {
    int e = blockIdx.x * blockDim.x + threadIdx.x;
    if (e >= NUM_K * EK) return;
    int k = e / EK;
    int s = ke[e];
    int d = ke[NUM_K * EK + e];
    int pos = atomicAdd(&g_cursor[k * Nn + d], 1);
    g_csr_src[k * EK + pos] = s;
}

// ---------------- embedding ----------------
__global__ void embed_kernel(const float* __restrict__ x,
                             const float* __restrict__ W,
                             const float* __restrict__ b) {
    __shared__ float ws[HID * 33];
    __shared__ float xs[16 * IN_D];
    int tid = threadIdx.x;              // 128
    int row0 = blockIdx.x * 16;
    for (int i = tid; i < HID * IN_D; i += 128) {
        int j = i / IN_D, kk = i - j * IN_D;
        ws[j * 33 + kk] = W[i];
    }
    for (int i = tid; i < 16 * IN_D; i += 128) xs[i] = x[row0 * IN_D + i];
    __syncthreads();
    float acc[16];
    float bb = b[tid];
#pragma unroll
    for (int r = 0; r < 16; r++) acc[r] = bb;
    for (int kk = 0; kk < IN_D; kk++) {
        float w = ws[tid * 33 + kk];
#pragma unroll
        for (int r = 0; r < 16; r++) acc[r] += xs[r * IN_D + kk] * w;
    }
#pragma unroll
    for (int r = 0; r < 16; r++)
        g_hist[(row0 + r) * HID + tid] = __float2half(acc[r]);
}

// ---------------- gather: input-layer-batched (all k on SAME hist[j]) ----------------
// For input layer j: blockIdx.y = km1 in [0, 4-j]; k = km1+1; output layer l = j+km1;
// writes z slot c_ci0[l] + km1.  z = dinv_d*(sum_e dinv_s*h[s] + dinv_d*h[d]); fp16 out.
// Inner loop identical to the proven R12 kernel (2 rows/warp, 16B loads, unroll-4).
__global__ __launch_bounds__(256) void gather_kernel(int j) {
    int warp = (blockIdx.x * 256 + threadIdx.x) >> 5;
    int lane = threadIdx.x & 31;
    int half = lane >> 4;                // 0 or 1
    int lx = lane & 15;                  // lane within half-warp
    int row = warp * 2 + half;
    if (row >= Nn) return;
    int km1 = blockIdx.y;
    int slot = c_ci0[j + km1] + km1;
    int e0 = g_rowstart[km1 * Nn + row];
    int e1 = e0 + (int)g_degcnt[km1 * Nn + row];
    const int* srcs = g_csr_src + km1 * EK;
    const float* dv = g_dinv + km1 * Nn;
    const __half* hin = g_hist + (size_t)j * Nn * HID;
    float sum[8];
#pragma unroll
    for (int i = 0; i < 8; i++) sum[i] = 0.f;
    int e = e0;
    for (; e + 3 < e1; e += 4) {
        int s0 = srcs[e], s1 = srcs[e + 1], s2 = srcs[e + 2], s3 = srcs[e + 3];
        float c0 = dv[s0], c1 = dv[s1], c2 = dv[s2], c3 = dv[s3];
        uint4 v0 = *(const uint4*)&hin[(size_t)s0 * HID + lx * 8];
        uint4 v1 = *(const uint4*)&hin[(size_t)s1 * HID + lx * 8];
        uint4 v2 = *(const uint4*)&hin[(size_t)s2 * HID + lx * 8];
        uint4 v3 = *(const uint4*)&hin[(size_t)s3 * HID + lx * 8];
        acc8(sum, v0, c0);
        acc8(sum, v1, c1);
        acc8(sum, v2, c2);
        acc8(sum, v3, c3);
    }
    for (; e < e1; e++) {
        int s0 = srcs[e];
        float c0 = dv[s0];
        uint4 v0 = *(const uint4*)&hin[(size_t)s0 * HID + lx * 8];
        acc8(sum, v0, c0);
    }
    float dd = dv[row];
    uint4 sfv = *(const uint4*)&hin[(size_t)row * HID + lx * 8];
    float self[8];
    {
        __half2 h0 = *(__half2*)&sfv.x, h1 = *(__half2*)&sfv.y;
        __half2 h2 = *(__half2*)&sfv.z, h3 = *(__half2*)&sfv.w;
        float2 f0 = __half22float2(h0), f1 = __half22float2(h1);
        float2 f2 = __half22float2(h2), f3 = __half22float2(h3);
        self[0] = f0.x; self[1] = f0.y; self[2] = f1.x; self[3] = f1.y;
        self[4] = f2.x; self[5] = f2.y; self[6] = f3.x; self[7] = f3.y;
    }
    __half2 r0 = __floats2half2_rn(dd * (sum[0] + dd * self[0]), dd * (sum[1] + dd * self[1]));
    __half2 r1 = __floats2half2_rn(dd * (sum[2] + dd * self[2]), dd * (sum[3] + dd * self[3]));
    __half2 r2 = __floats2half2_rn(dd * (sum[4] + dd * self[4]), dd * (sum[5] + dd * self[5]));
    __half2 r3 = __floats2half2_rn(dd * (sum[6] + dd * self[6]), dd * (sum[7] + dd * self[7]));
    uint4 st;
    st.x = *(uint32_t*)&r0; st.y = *(uint32_t*)&r1;
    st.z = *(uint32_t*)&r2; st.w = *(uint32_t*)&r3;
    size_t ofs = (size_t)slot * Nn * HID + (size_t)row * HID + lx * 8;
    *(uint4*)&g_z[ofs] = st;
}

// ---------------- layer GEMM via mma.sync f16 (A single, W hi/lo) ----------------
#define ASTR 136                        // fp16 elements per smem row (conflict-free)
#define TILE_B (128 * ASTR * 2)         // 34816 bytes per tile
#define OFF_A 0
#define OFF_WHI TILE_B
#define OFF_WLO (2 * TILE_B)
#define DYN_SMEM (3 * TILE_B)

__global__ __launch_bounds__(256, 1) void layer_gemm(int l, int nk) {
    extern __shared__ char smem[];
    int tid = threadIdx.x;
    int wid = tid >> 5, lane = tid & 31;
    int row0 = blockIdx.x * 128;
    int qr = lane >> 2;          // 0..7
    int qc = (lane & 3) * 2;     // 0,2,4,6
    int wm = (wid & 3) * 32;     // warp row offset
    int wn = (wid >> 2) * 64;    // warp col offset

    float acc[2][8][4];
#pragma unroll
    for (int mt = 0; mt < 2; mt++)
#pragma unroll
        for (int nt = 0; nt < 8; nt++)
#pragma unroll
            for (int c = 0; c < 4; c++) acc[mt][nt][c] = 0.f;

    int ci0 = c_ci0[l];
    for (int kk = 0; kk < nk; kk++) {
        // stage tiles: z slot (this block's rows) and W hi/lo, re-strided to ASTR
        const float4* za = (const float4*)(g_z + (size_t)(ci0 + kk) * Nn * HID);
        const float4* wh = (const float4*)(g_Wfhi + (size_t)(ci0 + kk) * HID * HID);
        const float4* wl = (const float4*)(g_Wflo + (size_t)(ci0 + kk) * HID * HID);
        for (int i = tid; i < 128 * 16; i += 256) {
            int r = i >> 4, c = i & 15;          // c in float4 (8 fp16) units
            int gr = row0 + r;
            float4 va = make_float4(0.f, 0.f, 0.f, 0.f);
            if (gr < Nn) va = za[(size_t)gr * 16 + c];
            size_t dofs = (size_t)r * (ASTR * 2) + c * 16;
            *(float4*)(smem + OFF_A + dofs) = va;
            *(float4*)(smem + OFF_WHI + dofs) = wh[i];
            *(float4*)(smem + OFF_WLO + dofs) = wl[i];
        }
        __syncthreads();

#pragma unroll
        for (int ks = 0; ks < 8; ks++) {
            int k0 = ks * 16;
            uint32_t ah[2][4];
#pragma unroll
            for (int mt = 0; mt < 2; mt++) {
                int r = wm + mt * 16 + qr;
                size_t b0 = (size_t)r * (ASTR * 2) + (k0 + qc) * 2;
                size_t b8 = b0 + 8 * (ASTR * 2);
                ah[mt][0] = *(const uint32_t*)(smem + OFF_A + b0);
                ah[mt][1] = *(const uint32_t*)(smem + OFF_A + b8);
                ah[mt][2] = *(const uint32_t*)(smem + OFF_A + b0 + 16);
                ah[mt][3] = *(const uint32_t*)(smem + OFF_A + b8 + 16);
            }
#pragma unroll
            for (int nt = 0; nt < 8; nt++) {
                int n = wn + nt * 8 + qr;
                size_t b0 = (size_t)n * (ASTR * 2) + (k0 + qc) * 2;
                uint32_t bh0 = *(const uint32_t*)(smem + OFF_WHI + b0);
                uint32_t bh1 = *(const uint32_t*)(smem + OFF_WHI + b0 + 16);
                uint32_t bl0 = *(const uint32_t*)(smem + OFF_WLO + b0);
                uint32_t bl1 = *(const uint32_t*)(smem + OFF_WLO + b0 + 16);
#pragma unroll
                for (int mt = 0; mt < 2; mt++) {
                    mma_f16(acc[mt][nt], ah[mt], bh0, bh1);
                    mma_f16(acc[mt][nt], ah[mt], bl0, bl1);
                }
            }
        }
        __syncthreads();
    }

    // epilogue: bias + relu, fp16 stores
    const float* bl_ = g_blayer + l * HID;
    __half* hout = g_hist + (size_t)(l + 1) * Nn * HID;
#pragma unroll
    for (int mt = 0; mt < 2; mt++) {
        int r = row0 + wm + mt * 16 + qr;
#pragma unroll
        for (int nt = 0; nt < 8; nt++) {
            int col = wn + nt * 8 + qc;
            float b0v = __ldg(&bl_[col]), b1v = __ldg(&bl_[col + 1]);
            if (r < Nn) {
                __half2 v = __floats2half2_rn(fmaxf(acc[mt][nt][0] + b0v, 0.f),
                                              fmaxf(acc[mt][nt][1] + b1v, 0.f));
                *(__half2*)&hout[(size_t)r * HID + col] = v;
            }
            if (r + 8 < Nn) {
                __half2 v = __floats2half2_rn(fmaxf(acc[mt][nt][2] + b0v, 0.f),
                                              fmaxf(acc[mt][nt][3] + b1v, 0.f));
                *(__half2*)&hout[(size_t)(r + 8) * HID + col] = v;
            }
        }
    }
}

// ---------------- pooling + readout ----------------
__global__ void pool_seg(const int* __restrict__ batch) {
    int n0 = blockIdx.x * 128;
    int tid = threadIdx.x;
    const __half* h = g_hist + (size_t)5 * Nn * HID;
    int nend = min(n0 + 128, Nn);
    int cur = batch[n0];
    float sum = 0.f, mx = 0.f;
    int cnt = 0;
    for (int n = n0; n < nend; n++) {
        int b = __ldg(&batch[n]);
        if (b != cur) {
            atomicAdd(&g_ssum[cur * HID + tid], sum);
            atomicMax((int*)&g_smax[cur * HID + tid], __float_as_int(mx));
            if (tid == 0) atomicAdd(&g_cnt[cur], (float)cnt);
            sum = 0.f; mx = 0.f; cnt = 0; cur = b;
        }
        float v = __half2float(h[(size_t)n * HID + tid]);
        sum += v; mx = fmaxf(mx, v); cnt++;
    }
    atomicAdd(&g_ssum[cur * HID + tid], sum);
    atomicMax((int*)&g_smax[cur * HID + tid], __float_as_int(mx));
    if (tid == 0) atomicAdd(&g_cnt[cur], (float)cnt);
}
__global__ void r1_kernel(const float* __restrict__ r1b) {
    __shared__ float ps[R1IN];
    int g = blockIdx.x, tid = threadIdx.x; // 192
    if (tid < HID) {
        float s = g_ssum[g * HID + tid];
        float m = g_smax[g * HID + tid];
        float c = g_cnt[g];
        ps[tid] = s;
        ps[HID + tid] = m;
        ps[2 * HID + tid] = s / fmaxf(c, 1.0f);
    }
    __syncthreads();
    float acc = r1b[tid];
    for (int c = 0; c < R1IN; c++) acc += ps[c] * g_r1Wt[c * RH + tid];
    g_hid[g * RH + tid] = acc > 0.0f ? acc : 0.01f * acc;
}
__global__ void r2_kernel(const float* __restrict__ r2b, float* __restrict__ out) {
    int idx = blockIdx.x * blockDim.x + threadIdx.x;
    if (idx >= NG * OUT_D) return;
    int g = idx / OUT_D, o = idx - g * OUT_D;
    float acc = r2b[o];
    for (int c = 0; c < RH; c++) acc += g_hid[g * RH + c] * g_r2Wt[c * OUT_D + o];
    out[idx] = acc;
}

extern "C" void kernel_launch(void* const* d_in, const int* in_sizes, int n_in,
                              void* d_out, int out_size) {
    const float* x     = (const float*)d_in[0];
    const int*   ke    = (const int*)d_in[1];
    // d_in[2] = k_idx (unused)
    const int*   batch = (const int*)d_in[3];
    const float* embW  = (const float*)d_in[4];
    const float* embb  = (const float*)d_in[5];
    const float* convW = (const float*)d_in[6];
    const float* convb = (const float*)d_in[7];
    const float* r1W   = (const float*)d_in[8];
    const float* r1b   = (const float*)d_in[9];
    const float* r2W   = (const float*)d_in[10];
    const float* r2b   = (const float*)d_in[11];
    float* out = (float*)d_out;

    cudaFuncSetAttribute(layer_gemm, cudaFuncAttributeMaxDynamicSharedMemorySize, DYN_SMEM);

    prep_weights<<<(RH * R1IN + 255) / 256, 256>>>(r1W, r2W);
    prep_wbf<<<(NC * HID * HID + 255) / 256, 256>>>(convW);
    prep_bias<<<1, 128>>>(convb);
    csr_zero<<<(NUM_K * Nn + 255) / 256, 256>>>();
    csr_count<<<(NUM_K * EK + 255) / 256, 256>>>(ke + NUM_K * EK);
    csr_alloc<<<(NUM_K * WPK * 32 + 255) / 256, 256>>>();
    csr_fill<<<(NUM_K * EK + 255) / 256, 256>>>(ke);
    embed_kernel<<<Nn / 16, 128>>>(x, embW, embb);

    // input-layer-batched schedule:
    // after hist[j] exists, compute A_k * hist[j] for all k=1..5-j (one launch),
    // then gemm(j) consumes its l+1 z-slots (all already written).
    for (int j = 0; j <= 4; j++) {
        dim3 ggrid((Nn + 15) / 16, 5 - j);   // 16 rows/block (8 warps x 2 rows)
        gather_kernel<<<ggrid, 256>>>(j);
        layer_gemm<<<(Nn + 127) / 128, 256, DYN_SMEM>>>(j, j + 1);
    }

    pool_seg<<<(Nn + 127) / 128, 128>>>(batch);
    r1_kernel<<<NG, RH>>>(r1b);
    r2_kernel<<<(NG * OUT_D + 255) / 256, 256>>>(r2b, out);
}

// round 16
// speedup vs baseline: 1.1526x; 1.0391x over previous
#include <cuda_runtime.h>
#include <cuda_bf16.h>
#include <cuda_fp16.h>
#include <cstdint>

#define Nn 50000
#define IN_D 32
#define HID 128
#define OUT_D 10
#define NUM_K 5
#define EK 400000
#define NG 500
#define NC 15
#define RH 192
#define R1IN 384

// ---------------- scratch (device globals) ----------------
__device__ __align__(256) __half g_hist[6 * Nn * HID];      // h0..h5 (fp16 storage, f32 math)
__device__ __align__(256) __half g_z[NC * Nn * HID];        // triangular z store: slot = c_ci0[l]+km1
__device__ __align__(256) __half g_Wfhi[NC * HID * HID];    // W/k fp16 hi, row-major [ci][n][k]
__device__ __align__(256) __half g_Wflo[NC * HID * HID];    // fp16 lo residual
__device__ __align__(256) float g_blayer[5 * HID];
__device__ __align__(256) float g_r1Wt[R1IN * RH];
__device__ __align__(256) float g_r2Wt[RH * OUT_D];
__device__ __align__(256) float g_dinv[NUM_K * Nn];
__device__ __align__(256) unsigned g_degcnt[NUM_K * Nn];
__device__ __align__(256) int g_rowstart[NUM_K * Nn];
__device__ __align__(256) int g_cursor[NUM_K * Nn];
__device__ __align__(256) int g_ctr[NUM_K];
__device__ __align__(256) int g_csr_src[NUM_K * EK];
__device__ __align__(256) float g_ssum[NG * HID];
__device__ __align__(256) float g_smax[NG * HID];
__device__ __align__(256) float g_cnt[NG];
__device__ __align__(256) float g_hid[NG * RH];

__constant__ int c_kval[NC] = {1, 1,2, 1,2,3, 1,2,3,4, 1,2,3,4,5};
__constant__ int c_ci0[5]   = {0, 1, 3, 6, 10};

// ---------------- helpers ----------------
__device__ __forceinline__ uint32_t smem_u32(const void* p) {
    uint32_t a;
    asm("{ .reg .u64 t; cvta.to.shared.u64 t, %1; cvt.u32.u64 %0, t; }" : "=r"(a) : "l"(p));
    return a;
}
__device__ __forceinline__ void mma_f16(float* c, const uint32_t* a, uint32_t b0, uint32_t b1) {
    asm volatile(
        "mma.sync.aligned.m16n8k16.row.col.f32.f16.f16.f32 "
        "{%0,%1,%2,%3}, {%4,%5,%6,%7}, {%8,%9}, {%0,%1,%2,%3};"
        : "+f"(c[0]), "+f"(c[1]), "+f"(c[2]), "+f"(c[3])
        : "r"(a[0]), "r"(a[1]), "r"(a[2]), "r"(a[3]), "r"(b0), "r"(b1));
}
__device__ __forceinline__ void cpasync16(uint32_t saddr, const void* gaddr) {
    asm volatile("cp.async.cg.shared.global [%0], [%1], 16;" :: "r"(saddr), "l"(gaddr));
}
#define CP_COMMIT() asm volatile("cp.async.commit_group;" ::: "memory")
#define CP_WAIT0()  asm volatile("cp.async.wait_group 0;" ::: "memory")
// accumulate 8 halves (16B, uint4) scaled by c into 8 float sums
__device__ __forceinline__ void acc8(float* s, uint4 v, float c) {
    __half2 h0 = *(__half2*)&v.x, h1 = *(__half2*)&v.y;
    __half2 h2 = *(__half2*)&v.z, h3 = *(__half2*)&v.w;
    float2 f0 = __half22float2(h0), f1 = __half22float2(h1);
    float2 f2 = __half22float2(h2), f3 = __half22float2(h3);
    s[0] += c * f0.x; s[1] += c * f0.y;
    s[2] += c * f1.x; s[3] += c * f1.y;
    s[4] += c * f2.x; s[5] += c * f2.y;
    s[6] += c * f3.x; s[7] += c * f3.y;
}

// ---------------- setup kernels ----------------
__global__ void prep_weights(const float* __restrict__ r1W, const float* __restrict__ r2W) {
    int idx = blockIdx.x * blockDim.x + threadIdx.x;
    if (idx < RH * R1IN) {
        int j = idx / R1IN, c = idx - j * R1IN;
        g_r1Wt[c * RH + j] = r1W[idx];
    }
    if (idx < OUT_D * RH) {
        int o = idx / RH, c = idx - o * RH;
        g_r2Wt[c * OUT_D + o] = r2W[idx];
    }
}
__global__ void prep_wbf(const float* __restrict__ convW) {
    int idx = blockIdx.x * blockDim.x + threadIdx.x;
    if (idx >= NC * HID * HID) return;
    int ci = idx / (HID * HID);
    float w = convW[idx] / (float)c_kval[ci];
    __half hi = __float2half_rn(w);
    __half lo = __float2half_rn(w - __half2float(hi));
    g_Wfhi[idx] = hi;
    g_Wflo[idx] = lo;
}
__global__ void prep_bias(const float* __restrict__ convb) {
    int j = threadIdx.x;  // 128
    for (int l = 0; l < 5; l++) {
        float s = 0.f;
        for (int kk = 0; kk <= l; kk++)
            s += convb[(c_ci0[l] + kk) * HID + j] / (float)(kk + 1);
        g_blayer[l * HID + j] = s;
    }
}

// ---------------- CSR build (+ pooling buffer zero, fused) ----------------
__global__ void csr_zero() {
    int idx = blockIdx.x * blockDim.x + threadIdx.x;
    if (idx < NUM_K * Nn) g_degcnt[idx] = 0u;
    if (idx < NUM_K) g_ctr[idx] = 0;
    if (idx < NG * HID) { g_ssum[idx] = 0.0f; g_smax[idx] = 0.0f; }
    if (idx < NG) g_cnt[idx] = 0.0f;
}
__global__ void csr_count(const int* __restrict__ dst_all) {
    int e = blockIdx.x * blockDim.x + threadIdx.x;
    if (e < NUM_K * EK) {
        int k = e / EK;
        atomicAdd(&g_degcnt[k * Nn + dst_all[e]], 1u);
    }
}
#define WPK ((Nn + 31) / 32)
__global__ void csr_alloc() {
    int gw = (blockIdx.x * blockDim.x + threadIdx.x) >> 5;
    int lane = threadIdx.x & 31;
    int k = gw / WPK;
    if (k >= NUM_K) return;
    int d = (gw - k * WPK) * 32 + lane;
    int c = (d < Nn) ? (int)g_degcnt[k * Nn + d] : 0;
    int incl = c;
#pragma unroll
    for (int off = 1; off < 32; off <<= 1) {
        int t = __shfl_up_sync(0xffffffff, incl, off);
        if (lane >= off) incl += t;
    }
    int total = __shfl_sync(0xffffffff, incl, 31);
    int base = 0;
    if (lane == 0) base = atomicAdd(&g_ctr[k], total);
    base = __shfl_sync(0xffffffff, base, 0);
    if (d < Nn) {
        int rs = base + incl - c;
        g_rowstart[k * Nn + d] = rs;
        g_cursor[k * Nn + d] = rs;
        g_dinv[k * Nn + d] = rsqrtf((float)c + 1.0f);
    }
}
__global__ void csr_fill(const int* __restrict__ ke) {
    int e = blockIdx.x * blockDim.x + threadIdx.x;
    if (e >= NUM_K * EK) return;
    int k = e / EK;
    int s = ke[e];
    int d = ke[NUM_K * EK + e];
    int pos = atomicAdd(&g_cursor[k * Nn + d], 1);
    g_csr_src[k * EK + pos] = s;
}

// ---------------- embedding ----------------
__global__ void embed_kernel(const float* __restrict__ x,
                             const float* __restrict__ W,
                             const float* __restrict__ b) {
    __shared__ float ws[HID * 33];
    __shared__ float xs[16 * IN_D];
    int tid = threadIdx.x;              // 128
    int row0 = blockIdx.x * 16;
    for (int i = tid; i < HID * IN_D; i += 128) {
        int j = i / IN_D, kk = i - j * IN_D;
        ws[j * 33 + kk] = W[i];
    }
    for (int i = tid; i < 16 * IN_D; i += 128) xs[i] = x[row0 * IN_D + i];
    __syncthreads();
    float acc[16];
    float bb = b[tid];
#pragma unroll
    for (int r = 0; r < 16; r++) acc[r] = bb;
    for (int kk = 0; kk < IN_D; kk++) {
        float w = ws[tid * 33 + kk];
#pragma unroll
        for (int r = 0; r < 16; r++) acc[r] += xs[r * IN_D + kk] * w;
    }
#pragma unroll
    for (int r = 0; r < 16; r++)
        g_hist[(row0 + r) * HID + tid] = __float2half(acc[r]);
}

// ---------------- gather: input-layer-batched (R14 proven version) ----------------
__global__ __launch_bounds__(256) void gather_kernel(int j) {
    int warp = (blockIdx.x * 256 + threadIdx.x) >> 5;
    int lane = threadIdx.x & 31;
    int half = lane >> 4;                // 0 or 1
    int lx = lane & 15;                  // lane within half-warp
    int row = warp * 2 + half;
    if (row >= Nn) return;
    int km1 = blockIdx.y;
    int slot = c_ci0[j + km1] + km1;
    int e0 = g_rowstart[km1 * Nn + row];
    int e1 = e0 + (int)g_degcnt[km1 * Nn + row];
    const int* srcs = g_csr_src + km1 * EK;
    const float* dv = g_dinv + km1 * Nn;
    const __half* hin = g_hist + (size_t)j * Nn * HID;
    float sum[8];
#pragma unroll
    for (int i = 0; i < 8; i++) sum[i] = 0.f;
    int e = e0;
    for (; e + 3 < e1; e += 4) {
        int s0 = srcs[e], s1 = srcs[e + 1], s2 = srcs[e + 2], s3 = srcs[e + 3];
        float c0 = dv[s0], c1 = dv[s1], c2 = dv[s2], c3 = dv[s3];
        uint4 v0 = *(const uint4*)&hin[(size_t)s0 * HID + lx * 8];
        uint4 v1 = *(const uint4*)&hin[(size_t)s1 * HID + lx * 8];
        uint4 v2 = *(const uint4*)&hin[(size_t)s2 * HID + lx * 8];
        uint4 v3 = *(const uint4*)&hin[(size_t)s3 * HID + lx * 8];
        acc8(sum, v0, c0);
        acc8(sum, v1, c1);
        acc8(sum, v2, c2);
        acc8(sum, v3, c3);
    }
    for (; e < e1; e++) {
        int s0 = srcs[e];
        float c0 = dv[s0];
        uint4 v0 = *(const uint4*)&hin[(size_t)s0 * HID + lx * 8];
        acc8(sum, v0, c0);
    }
    float dd = dv[row];
    uint4 sfv = *(const uint4*)&hin[(size_t)row * HID + lx * 8];
    float self[8];
    {
        __half2 h0 = *(__half2*)&sfv.x, h1 = *(__half2*)&sfv.y;
        __half2 h2 = *(__half2*)&sfv.z, h3 = *(__half2*)&sfv.w;
        float2 f0 = __half22float2(h0), f1 = __half22float2(h1);
        float2 f2 = __half22float2(h2), f3 = __half22float2(h3);
        self[0] = f0.x; self[1] = f0.y; self[2] = f1.x; self[3] = f1.y;
        self[4] = f2.x; self[5] = f2.y; self[6] = f3.x; self[7] = f3.y;
    }
    __half2 r0 = __floats2half2_rn(dd * (sum[0] + dd * self[0]), dd * (sum[1] + dd * self[1]));
    __half2 r1 = __floats2half2_rn(dd * (sum[2] + dd * self[2]), dd * (sum[3] + dd * self[3]));
    __half2 r2 = __floats2half2_rn(dd * (sum[4] + dd * self[4]), dd * (sum[5] + dd * self[5]));
    __half2 r3 = __floats2half2_rn(dd * (sum[6] + dd * self[6]), dd * (sum[7] + dd * self[7]));
    uint4 st;
    st.x = *(uint32_t*)&r0; st.y = *(uint32_t*)&r1;
    st.z = *(uint32_t*)&r2; st.w = *(uint32_t*)&r3;
    size_t ofs = (size_t)slot * Nn * HID + (size_t)row * HID + lx * 8;
    *(uint4*)&g_z[ofs] = st;
}

// ---------------- layer GEMM: f16 mma + cp.async double-buffered staging ----------------
#define ASTR 136                        // fp16 elements per smem row (conflict-free)
#define TILE_B (128 * ASTR * 2)         // 34816 bytes per tile
#define BUF_B (3 * TILE_B)              // A + Whi + Wlo per buffer
#define OFF_A 0
#define OFF_WHI TILE_B
#define OFF_WLO (2 * TILE_B)
#define DYN_SMEM (2 * BUF_B)            // 208896 bytes

__global__ __launch_bounds__(256, 1) void layer_gemm(int l, int nk) {
    extern __shared__ char smem[];
    uint32_t sb = smem_u32(smem);
    int tid = threadIdx.x;
    int wid = tid >> 5, lane = tid & 31;
    int row0 = blockIdx.x * 128;
    int qr = lane >> 2;          // 0..7
    int qc = (lane & 3) * 2;     // 0,2,4,6
    int wm = (wid & 3) * 32;     // warp row offset
    int wn = (wid >> 2) * 64;    // warp col offset
    int ci0 = c_ci0[l];

    float acc[2][8][4];
#pragma unroll
    for (int mt = 0; mt < 2; mt++)
#pragma unroll
        for (int nt = 0; nt < 8; nt++)
#pragma unroll
            for (int c = 0; c < 4; c++) acc[mt][nt][c] = 0.f;

    // stage tile kk into buffer buf (cp.async; OOB rows zero-filled via STS)
    auto stage = [&](int kk, int buf) {
        const char* za = (const char*)(g_z + (size_t)(ci0 + kk) * Nn * HID);
        const char* wh = (const char*)(g_Wfhi + (size_t)(ci0 + kk) * HID * HID);
        const char* wl = (const char*)(g_Wflo + (size_t)(ci0 + kk) * HID * HID);
        uint32_t base = sb + buf * BUF_B;
        for (int i = tid; i < 128 * 16; i += 256) {
            int r = i >> 4, c = i & 15;          // c in 16B units
            int gr = row0 + r;
            uint32_t dofs = (uint32_t)r * (ASTR * 2) + c * 16;
            size_t gofs = (size_t)r * 256 + c * 16;
            if (gr < Nn) {
                cpasync16(base + OFF_A + dofs, za + (size_t)gr * 256 + c * 16);
            } else {
                *(float4*)(smem + buf * BUF_B + OFF_A + dofs) = make_float4(0.f, 0.f, 0.f, 0.f);
            }
            cpasync16(base + OFF_WHI + dofs, wh + gofs);
            cpasync16(base + OFF_WLO + dofs, wl + gofs);
        }
        CP_COMMIT();
    };

    stage(0, 0);
    CP_WAIT0();
    __syncthreads();

    for (int kk = 0; kk < nk; kk++) {
        int cur = kk & 1;
        if (kk + 1 < nk) stage(kk + 1, cur ^ 1);   // prefetch next tile (overlaps MMA)

        const char* bufp = smem + cur * BUF_B;
#pragma unroll
        for (int ks = 0; ks < 8; ks++) {
            int k0 = ks * 16;
            uint32_t ah[2][4];
#pragma unroll
            for (int mt = 0; mt < 2; mt++) {
                int r = wm + mt * 16 + qr;
                size_t b0 = (size_t)r * (ASTR * 2) + (k0 + qc) * 2;
                size_t b8 = b0 + 8 * (ASTR * 2);
                ah[mt][0] = *(const uint32_t*)(bufp + OFF_A + b0);
                ah[mt][1] = *(const uint32_t*)(bufp + OFF_A + b8);
                ah[mt][2] = *(const uint32_t*)(bufp + OFF_A + b0 + 16);
                ah[mt][3] = *(const uint32_t*)(bufp + OFF_A + b8 + 16);
            }
#pragma unroll
            for (int nt = 0; nt < 8; nt++) {
                int n = wn + nt * 8 + qr;
                size_t b0 = (size_t)n * (ASTR * 2) + (k0 + qc) * 2;
                uint32_t bh0 = *(const uint32_t*)(bufp + OFF_WHI + b0);
                uint32_t bh1 = *(const uint32_t*)(bufp + OFF_WHI + b0 + 16);
                uint32_t bl0 = *(const uint32_t*)(bufp + OFF_WLO + b0);
                uint32_t bl1 = *(const uint32_t*)(bufp + OFF_WLO + b0 + 16);
#pragma unroll
                for (int mt = 0; mt < 2; mt++) {
                    mma_f16(acc[mt][nt], ah[mt], bh0, bh1);
                    mma_f16(acc[mt][nt], ah[mt], bl0, bl1);
                }
            }
        }
        if (kk + 1 < nk) CP_WAIT0();
        __syncthreads();
    }

    // epilogue: bias + relu, fp16 stores
    const float* bl_ = g_blayer + l * HID;
    __half* hout = g_hist + (size_t)(l + 1) * Nn * HID;
#pragma unroll
    for (int mt = 0; mt < 2; mt++) {
        int r = row0 + wm + mt * 16 + qr;
#pragma unroll
        for (int nt = 0; nt < 8; nt++) {
            int col = wn + nt * 8 + qc;
            float b0v = __ldg(&bl_[col]), b1v = __ldg(&bl_[col + 1]);
            if (r < Nn) {
                __half2 v = __floats2half2_rn(fmaxf(acc[mt][nt][0] + b0v, 0.f),
                                              fmaxf(acc[mt][nt][1] + b1v, 0.f));
                *(__half2*)&hout[(size_t)r * HID + col] = v;
            }
            if (r + 8 < Nn) {
                __half2 v = __floats2half2_rn(fmaxf(acc[mt][nt][2] + b0v, 0.f),
                                              fmaxf(acc[mt][nt][3] + b1v, 0.f));
                *(__half2*)&hout[(size_t)(r + 8) * HID + col] = v;
            }
        }
    }
}

// ---------------- pooling + readout ----------------
__global__ void pool_seg(const int* __restrict__ batch) {
    int n0 = blockIdx.x * 128;
    int tid = threadIdx.x;
    const __half* h = g_hist + (size_t)5 * Nn * HID;
    int nend = min(n0 + 128, Nn);
    int cur = batch[n0];
    float sum = 0.f, mx = 0.f;
    int cnt = 0;
    for (int n = n0; n < nend; n++) {
        int b = __ldg(&batch[n]);
        if (b != cur) {
            atomicAdd(&g_ssum[cur * HID + tid], sum);
            atomicMax((int*)&g_smax[cur * HID + tid], __float_as_int(mx));
            if (tid == 0) atomicAdd(&g_cnt[cur], (float)cnt);
            sum = 0.f; mx = 0.f; cnt = 0; cur = b;
        }
        float v = __half2float(h[(size_t)n * HID + tid]);
        sum += v; mx = fmaxf(mx, v); cnt++;
    }
    atomicAdd(&g_ssum[cur * HID + tid], sum);
    atomicMax((int*)&g_smax[cur * HID + tid], __float_as_int(mx));
    if (tid == 0) atomicAdd(&g_cnt[cur], (float)cnt);
}
__global__ void r1_kernel(const float* __restrict__ r1b) {
    __shared__ float ps[R1IN];
    int g = blockIdx.x, tid = threadIdx.x; // 192
    if (tid < HID) {
        float s = g_ssum[g * HID + tid];
        float m = g_smax[g * HID + tid];
        float c = g_cnt[g];
        ps[tid] = s;
        ps[HID + tid] = m;
        ps[2 * HID + tid] = s / fmaxf(c, 1.0f);
    }
    __syncthreads();
    float acc = r1b[tid];
    for (int c = 0; c < R1IN; c++) acc += ps[c] * g_r1Wt[c * RH + tid];
    g_hid[g * RH + tid] = acc > 0.0f ? acc : 0.01f * acc;
}
__global__ void r2_kernel(const float* __restrict__ r2b, float* __restrict__ out) {
    int idx = blockIdx.x * blockDim.x + threadIdx.x;
    if (idx >= NG * OUT_D) return;
    int g = idx / OUT_D, o = idx - g * OUT_D;
    float acc = r2b[o];
    for (int c = 0; c < RH; c++) acc += g_hid[g * RH + c] * g_r2Wt[c * OUT_D + o];
    out[idx] = acc;
}

extern "C" void kernel_launch(void* const* d_in, const int* in_sizes, int n_in,
                              void* d_out, int out_size) {
    const float* x     = (const float*)d_in[0];
    const int*   ke    = (const int*)d_in[1];
    // d_in[2] = k_idx (unused)
    const int*   batch = (const int*)d_in[3];
    const float* embW  = (const float*)d_in[4];
    const float* embb  = (const float*)d_in[5];
    const float* convW = (const float*)d_in[6];
    const float* convb = (const float*)d_in[7];
    const float* r1W   = (const float*)d_in[8];
    const float* r1b   = (const float*)d_in[9];
    const float* r2W   = (const float*)d_in[10];
    const float* r2b   = (const float*)d_in[11];
    float* out = (float*)d_out;

    cudaFuncSetAttribute(layer_gemm, cudaFuncAttributeMaxDynamicSharedMemorySize, DYN_SMEM);

    prep_weights<<<(RH * R1IN + 255) / 256, 256>>>(r1W, r2W);
    prep_wbf<<<(NC * HID * HID + 255) / 256, 256>>>(convW);
    prep_bias<<<1, 128>>>(convb);
    csr_zero<<<(NUM_K * Nn + 255) / 256, 256>>>();
    csr_count<<<(NUM_K * EK + 255) / 256, 256>>>(ke + NUM_K * EK);
    csr_alloc<<<(NUM_K * WPK * 32 + 255) / 256, 256>>>();
    csr_fill<<<(NUM_K * EK + 255) / 256, 256>>>(ke);
    embed_kernel<<<Nn / 16, 128>>>(x, embW, embb);

    // input-layer-batched schedule (R14)
    for (int j = 0; j <= 4; j++) {
        dim3 ggrid((Nn + 15) / 16, 5 - j);   // 16 rows/block (8 warps x 2 rows)
        gather_kernel<<<ggrid, 256>>>(j);
        layer_gemm<<<(Nn + 127) / 128, 256, DYN_SMEM>>>(j, j + 1);
    }

    pool_seg<<<(Nn + 127) / 128, 128>>>(batch);
    r1_kernel<<<NG, RH>>>(r1b);
    r2_kernel<<<(NG * OUT_D + 255) / 256, 256>>>(r2b, out);
}